// round 1
// baseline (speedup 1.0000x reference)
#include <cuda_runtime.h>

// HMM forward: alpha_t = (alpha_{t-1} @ A) * B[:, obs_t],  out = sum(alpha_{T-1})
// Persistent cooperative kernel. A (16 MB) lives permanently in registers:
// 128 blocks x 256 threads x 128 floats. Per step only the 8 KB alpha vector
// moves (L2 ping-pong + SMEM broadcast), then a grid-wide barrier.

namespace {
constexpr int GRID = 128;
constexpr int NT   = 256;
constexpr int S    = 2048;
constexpr int V    = 32768;
constexpr int T    = 4096;
constexpr int NCOL = S / GRID;  // 16 output columns per block
}

__device__ float    g_alpha[2][S];
__device__ unsigned g_arrive = 0;
__device__ unsigned g_gen    = 0;

__device__ __forceinline__ void grid_sync(unsigned target) {
    __syncthreads();
    if (threadIdx.x == 0) {
        unsigned a = atomicAdd(&g_arrive, 1u);
        if (a == GRID - 1) {
            g_arrive = 0u;            // reset before release; ordered by fence below
            __threadfence();
            atomicExch(&g_gen, target);
        } else {
            volatile unsigned* p = &g_gen;
            while (*p != target) { }
        }
        __threadfence();              // acquire
    }
    __syncthreads();
}

__global__ void __launch_bounds__(NT, 1) hmm_forward_kernel(
    const int*   __restrict__ obs,
    const float* __restrict__ A,
    const float* __restrict__ B,
    const float* __restrict__ pi,
    float*       __restrict__ out)
{
    __shared__ float4 alpha_s[S / 4];     // 8 KB: current alpha vector
    __shared__ float  red[2][NCOL];       // cross-rowgroup partials

    const int tid  = threadIdx.x;
    const int blk  = blockIdx.x;
    const int w    = tid >> 5;
    const int lane = tid & 31;
    const int cg   = w & 3;               // column group 0..3 (4 cols each)
    const int rg   = w >> 2;              // row group 0..1 (1024 rows each)
    const int jb   = blk * NCOL + cg * 4; // first of this warp's 4 columns
    const int rbase4 = rg * 256;          // float4 base index into alpha_s

    // ---- Load A tile into registers (one time) ----
    // Thread covers rows rbase + 4*lane + 128*k + rr (k<8, rr<4), cols jb..jb+3.
    float4 areg[8][4];
#pragma unroll
    for (int k = 0; k < 8; k++) {
#pragma unroll
        for (int rr = 0; rr < 4; rr++) {
            int row = rg * 1024 + 4 * lane + 128 * k + rr;
            areg[k][rr] = *reinterpret_cast<const float4*>(&A[(size_t)row * S + jb]);
        }
    }

    // Replay-safe barrier generations: relative to whatever g_gen holds at entry.
    const unsigned gen0 = g_gen;
    unsigned sync_cnt = 0;

    // ---- Init: alpha0 = pi * B[:, obs[0]]; zero the output scalar ----
    if (blk == 0 && tid == 0) *out = 0.0f;
    if (tid < NCOL) {
        int   j  = blk * NCOL + tid;
        int   o0 = __ldg(&obs[0]);
        float v  = pi[j] * __ldg(&B[(size_t)j * V + o0]);
        __stcg(&g_alpha[0][j], v);
    }
    __threadfence();
    sync_cnt++;
    grid_sync(gen0 + sync_cnt);

    int cur = 0;
    for (int s = 1; s < T; s++) {
        // Prefetch this step's emission factors early (independent of alpha).
        float bj = 0.0f;
        if (tid < NCOL) {
            int o = __ldg(&obs[s]);
            bj = __ldg(&B[(size_t)(blk * NCOL + tid) * V + o]);
        }

        // Stage alpha (L2 -> SMEM), bypassing L1 (previous-step lines are stale).
        const float4* ga = reinterpret_cast<const float4*>(g_alpha[cur]);
        alpha_s[tid]       = __ldcg(ga + tid);
        alpha_s[tid + 256] = __ldcg(ga + tid + 256);
        __syncthreads();

        // ---- Matvec slice: 128 FMAs per thread, A from registers ----
        float acc0 = 0.f, acc1 = 0.f, acc2 = 0.f, acc3 = 0.f;
#pragma unroll
        for (int k = 0; k < 8; k++) {
            float4 av = alpha_s[rbase4 + k * 32 + lane];
            float4 a0 = areg[k][0], a1 = areg[k][1], a2 = areg[k][2], a3 = areg[k][3];
            acc0 = fmaf(av.x, a0.x, acc0);
            acc1 = fmaf(av.x, a0.y, acc1);
            acc2 = fmaf(av.x, a0.z, acc2);
            acc3 = fmaf(av.x, a0.w, acc3);
            acc0 = fmaf(av.y, a1.x, acc0);
            acc1 = fmaf(av.y, a1.y, acc1);
            acc2 = fmaf(av.y, a1.z, acc2);
            acc3 = fmaf(av.y, a1.w, acc3);
            acc0 = fmaf(av.z, a2.x, acc0);
            acc1 = fmaf(av.z, a2.y, acc1);
            acc2 = fmaf(av.z, a2.z, acc2);
            acc3 = fmaf(av.z, a2.w, acc3);
            acc0 = fmaf(av.w, a3.x, acc0);
            acc1 = fmaf(av.w, a3.y, acc1);
            acc2 = fmaf(av.w, a3.z, acc2);
            acc3 = fmaf(av.w, a3.w, acc3);
        }

        // Warp reduce (rows are split across lanes).
#pragma unroll
        for (int off = 16; off > 0; off >>= 1) {
            acc0 += __shfl_xor_sync(0xffffffffu, acc0, off);
            acc1 += __shfl_xor_sync(0xffffffffu, acc1, off);
            acc2 += __shfl_xor_sync(0xffffffffu, acc2, off);
            acc3 += __shfl_xor_sync(0xffffffffu, acc3, off);
        }
        if (lane == 0) {
            red[rg][cg * 4 + 0] = acc0;
            red[rg][cg * 4 + 1] = acc1;
            red[rg][cg * 4 + 2] = acc2;
            red[rg][cg * 4 + 3] = acc3;
        }
        __syncthreads();

        if (tid < NCOL) {
            float v = (red[0][tid] + red[1][tid]) * bj;
            if (s == T - 1) {
                atomicAdd(out, v);
            } else {
                __stcg(&g_alpha[cur ^ 1][blk * NCOL + tid], v);
                __threadfence();
            }
        }

        if (s != T - 1) {
            sync_cnt++;
            grid_sync(gen0 + sync_cnt);
        }
        cur ^= 1;
    }
}

extern "C" void kernel_launch(void* const* d_in, const int* in_sizes, int n_in,
                              void* d_out, int out_size) {
    const int*   obs = (const int*)d_in[0];
    const float* A   = (const float*)d_in[1];
    const float* B   = (const float*)d_in[2];
    const float* pi  = (const float*)d_in[3];
    float*       out = (float*)d_out;
    (void)in_sizes; (void)n_in; (void)out_size;

    hmm_forward_kernel<<<GRID, NT>>>(obs, A, B, pi, out);
}